// round 2
// baseline (speedup 1.0000x reference)
#include <cuda_runtime.h>

// ---------------------------------------------------------------------------
// SlotAttention fused kernel. B=32, N=16384, S=8, D=64, H=128, ITERS=3.
//
// Per iteration, the only O(N) work is a single fused pass over raw x:
//   d[s]    = x_row . (ln_in_g * qtilde[s])
//   logit_s = istd*(d[s] - m*c1[s]) + c0[s]          (input LN folded)
//   a_s     = softmax_s(logit) + EPS                  (row softmax over 8)
//   Pacc[s,e] += (a_s*istd) * x_row[e]                (rank-1 accumulation)
//   Sg[s] += a_s ;   Sb[s] += a_s*m*istd
// Then per batch (tiny):
//   U[s,e]  = (g_e*(Pacc-Sb[s]) + b_e*Sg[s]) / Sg[s]  (colsum-normalized)
//   updates = U @ Wv^T ; GRU ; residual MLP ; new slots ; prep next weights
// ---------------------------------------------------------------------------

#define BB 32
#define NN 16384
#define SS 8
#define DD 64
#define HH 128
#define NBLKX 64                 // pass blocks per batch
#define ROWS_PER_BLOCK 256
#define TILE_ROWS 128
#define NTILES 2
#define PREC 528                 // 512 Pacc + 8 Sg + 8 Sb
#define PASS_THREADS 128

__device__ float  g_slots[BB * SS * DD];
__device__ float4 g_wts4[BB * 128];            // [b][k=0..15][s=0..7] float4
__device__ float  g_c0[BB][SS];
__device__ float  g_c1[BB][SS];
__device__ float  g_part[(size_t)BB * NBLKX * PREC];

__device__ __forceinline__ float sigm(float x) {
    return 1.f / (1.f + __expf(-x));
}

// ---------------------------------------------------------------------------
// prep: from slots (in shared) compute the folded pass weights for next pass
// ---------------------------------------------------------------------------
__device__ __forceinline__ void prep_body(
    int b, int t,
    const float (*sl)[64], float (*lns)[64], float (*q)[64], float (*qt)[64],
    const float* __restrict__ lnsg, const float* __restrict__ lnsb,
    const float* __restrict__ Wq,   const float* __restrict__ Wk,
    const float* __restrict__ lng,  const float* __restrict__ lnb)
{
    int w = t >> 5, l = t & 31;
    // LayerNorm of slots: warp w handles slot w
    {
        float v0 = sl[w][l], v1 = sl[w][l + 32];
        float sum = v0 + v1;
        float sq  = fmaf(v0, v0, v1 * v1);
#pragma unroll
        for (int off = 16; off; off >>= 1) {
            sum += __shfl_xor_sync(0xffffffffu, sum, off);
            sq  += __shfl_xor_sync(0xffffffffu, sq,  off);
        }
        float m    = sum * (1.f / 64.f);
        float istd = rsqrtf(fmaf(sq, 1.f / 64.f, -m * m) + 1e-5f);
        lns[w][l]      = fmaf((v0 - m) * istd, lnsg[l],      lnsb[l]);
        lns[w][l + 32] = fmaf((v1 - m) * istd, lnsg[l + 32], lnsb[l + 32]);
    }
    __syncthreads();
    // q = LN(slots) @ Wq^T * D^-0.5
    for (int i = t; i < 512; i += 256) {
        int s = i >> 6, dd = i & 63;
        float acc = 0.f;
        const float* wr = Wq + dd * 64;
#pragma unroll 8
        for (int e = 0; e < 64; ++e) acc = fmaf(lns[s][e], wr[e], acc);
        q[s][dd] = acc * 0.125f;
    }
    __syncthreads();
    // qtilde = q @ Wk
    for (int i = t; i < 512; i += 256) {
        int s = i >> 6, e = i & 63;
        float acc = 0.f;
#pragma unroll 8
        for (int dd = 0; dd < 64; ++dd) acc = fmaf(q[s][dd], Wk[dd * 64 + e], acc);
        qt[s][e] = acc;
    }
    __syncthreads();
    // pass weights: wts[k][s].j = ln_in_g[4k+j] * qtilde[s][4k+j]
    float* wout = reinterpret_cast<float*>(g_wts4 + b * 128);
    for (int i = t; i < 512; i += 256) {
        int s = i >> 6, e = i & 63;
        int k = e >> 2, j = e & 3;
        wout[(k * 8 + s) * 4 + j] = lng[e] * qt[s][e];
    }
    if (t < 8) {
        float a0 = 0.f, a1 = 0.f;
#pragma unroll 8
        for (int e = 0; e < 64; ++e) {
            a1 = fmaf(lng[e], qt[t][e], a1);
            a0 = fmaf(lnb[e], qt[t][e], a0);
        }
        g_c1[b][t] = a1;
        g_c0[b][t] = a0;
    }
}

// ---------------------------------------------------------------------------
// init: slots = mu + exp(log_sigma)*noise, then prep for iter 0
// ---------------------------------------------------------------------------
__global__ void __launch_bounds__(256) k_init(
    const float* __restrict__ noise, const float* __restrict__ mu,
    const float* __restrict__ lsig,
    const float* __restrict__ lnsg, const float* __restrict__ lnsb,
    const float* __restrict__ Wq,   const float* __restrict__ Wk,
    const float* __restrict__ lng,  const float* __restrict__ lnb)
{
    __shared__ float sl[8][64], lns[8][64], q[8][64], qt[8][64];
    int b = blockIdx.x, t = threadIdx.x;
    for (int i = t; i < 512; i += 256) {
        float v = fmaf(__expf(lsig[i]), noise[b * 512 + i], mu[i]);
        sl[i >> 6][i & 63] = v;
        g_slots[b * 512 + i] = v;
    }
    __syncthreads();
    prep_body(b, t, sl, lns, q, qt, lnsg, lnsb, Wq, Wk, lng, lnb);
}

// ---------------------------------------------------------------------------
// the big fused pass over x (>90% of runtime)
// ---------------------------------------------------------------------------
__global__ void __launch_bounds__(PASS_THREADS, 5) k_pass(const float4* __restrict__ x4)
{
    __shared__ float4 xs[TILE_ROWS * 16];   // 128 rows x 16 float4, swizzled (32KB)
    __shared__ float4 as4[TILE_ROWS * 2];   // per-row alpha*istd, 8 slots (4KB)
    __shared__ float4 wts[128];             // [k][s] folded weights (2KB)
    __shared__ float  c0s[8], c1s[8];
    __shared__ float  redSg[4][8], redSb[4][8];

    const int b = blockIdx.y;
    const int t = threadIdx.x;            // 0..127
    const int w = t >> 5, l = t & 31;

    wts[t] = g_wts4[b * 128 + t];
    if (t < 8) { c0s[t] = g_c0[b][t]; c1s[t] = g_c1[b][t]; }

    float c0r[8], c1r[8];
    float gacc[8], bacc[8];
    float pacc[4] = {0.f, 0.f, 0.f, 0.f};

    const float4* xb = x4 + ((size_t)b * NN + (size_t)blockIdx.x * ROWS_PER_BLOCK) * 16;

    // rank-1 ownership: slot group g2 (slots 2g2, 2g2+1), element pair p
    const int g2   = t >> 5;
    const int p    = t & 31;
    const int k4   = p >> 1;
    const int half = p & 1;

#pragma unroll 1
    for (int tt = 0; tt < NTILES; ++tt) {
        // ---- stage 128 rows, coalesced -> swizzled smem ----
        const float4* src = xb + (size_t)tt * TILE_ROWS * 16;
        const int kst = t & 15;
#pragma unroll
        for (int j = 0; j < 16; ++j) {
            int flat = j * 128 + t;
            int row  = flat >> 4;
            xs[row * 16 + (kst ^ (row & 15))] = src[flat];
        }
        __syncthreads();
        if (tt == 0) {
#pragma unroll
            for (int s = 0; s < 8; ++s) { c0r[s] = c0s[s]; c1r[s] = c1s[s];
                                          gacc[s] = 0.f;   bacc[s] = 0.f; }
        }

        // ---- lane t owns row t: LN stats + 8 folded dots, softmax ----
        {
            float sum = 0.f, sq = 0.f;
            float d[8];
#pragma unroll
            for (int s = 0; s < 8; ++s) d[s] = 0.f;
            const int xbase = t * 16, xo = t & 15;
#pragma unroll
            for (int k = 0; k < 16; ++k) {
                float4 v = xs[xbase + (k ^ xo)];
                sum += v.x + v.y + v.z + v.w;
                sq = fmaf(v.x, v.x, sq); sq = fmaf(v.y, v.y, sq);
                sq = fmaf(v.z, v.z, sq); sq = fmaf(v.w, v.w, sq);
#pragma unroll
                for (int s = 0; s < 8; ++s) {
                    float4 wv = wts[k * 8 + s];
                    d[s] = fmaf(v.x, wv.x, d[s]);
                    d[s] = fmaf(v.y, wv.y, d[s]);
                    d[s] = fmaf(v.z, wv.z, d[s]);
                    d[s] = fmaf(v.w, wv.w, d[s]);
                }
            }
            float m    = sum * (1.f / 64.f);
            float istd = rsqrtf(fmaf(sq, 1.f / 64.f, -m * m) + 1e-5f);
            float lo[8], mx = -3.4e38f;
#pragma unroll
            for (int s = 0; s < 8; ++s) {
                lo[s] = fmaf(istd, fmaf(-m, c1r[s], d[s]), c0r[s]);
                mx = fmaxf(mx, lo[s]);
            }
            float pr[8], ps = 0.f;
#pragma unroll
            for (int s = 0; s < 8; ++s) { pr[s] = __expf(lo[s] - mx); ps += pr[s]; }
            float rc  = 1.f / ps;
            float tmi = m * istd;
            float al[8];
#pragma unroll
            for (int s = 0; s < 8; ++s) {
                float a = fmaf(pr[s], rc, 1e-8f);   // softmax + EPS
                gacc[s] += a;                       // Sg partial
                bacc[s] = fmaf(a, tmi, bacc[s]);    // Sb partial
                al[s]   = a * istd;                 // Pacc weight
            }
            as4[t * 2 + 0] = make_float4(al[0], al[1], al[2], al[3]);
            as4[t * 2 + 1] = make_float4(al[4], al[5], al[6], al[7]);
        }
        __syncthreads();

        // ---- rank-1: lane owns (slots 2g2,2g2+1) x (elements 2p,2p+1) ----
        {
            const float2* x2 = reinterpret_cast<const float2*>(xs);
            const float2* a2 = reinterpret_cast<const float2*>(as4);
#pragma unroll 4
            for (int r = 0; r < TILE_ROWS; ++r) {
                float2 av = a2[r * 4 + g2];
                float2 xv = x2[((r * 16 + (k4 ^ (r & 15))) << 1) + half];
                pacc[0] = fmaf(av.x, xv.x, pacc[0]);
                pacc[1] = fmaf(av.x, xv.y, pacc[1]);
                pacc[2] = fmaf(av.y, xv.x, pacc[2]);
                pacc[3] = fmaf(av.y, xv.y, pacc[3]);
            }
        }
        __syncthreads();   // xs/as4 reuse next tile
    }

    // ---- deterministic per-block partial record ----
#pragma unroll
    for (int s = 0; s < 8; ++s) {
        float gv = gacc[s], bv = bacc[s];
#pragma unroll
        for (int off = 16; off; off >>= 1) {
            gv += __shfl_xor_sync(0xffffffffu, gv, off);
            bv += __shfl_xor_sync(0xffffffffu, bv, off);
        }
        if (l == 0) { redSg[w][s] = gv; redSb[w][s] = bv; }
    }
    __syncthreads();

    float* base = g_part + ((size_t)b * NBLKX + blockIdx.x) * PREC;
    float2* bp2 = reinterpret_cast<float2*>(base);
    const int s0 = 2 * g2;
    bp2[(s0 + 0) * 32 + p] = make_float2(pacc[0], pacc[1]);
    bp2[(s0 + 1) * 32 + p] = make_float2(pacc[2], pacc[3]);
    if (t < 8) {
        base[512 + t] = ((redSg[0][t] + redSg[1][t]) + redSg[2][t]) + redSg[3][t];
        base[520 + t] = ((redSb[0][t] + redSb[1][t]) + redSb[2][t]) + redSb[3][t];
    }
}

// ---------------------------------------------------------------------------
// slot update: reduce partials, Wv, GRU, MLP; write slots/out; prep next iter
// ---------------------------------------------------------------------------
__global__ void __launch_bounds__(256) k_update(
    const float* __restrict__ lng,  const float* __restrict__ lnb,
    const float* __restrict__ lnsg, const float* __restrict__ lnsb,
    const float* __restrict__ lnmg, const float* __restrict__ lnmb,
    const float* __restrict__ Wq,   const float* __restrict__ Wk,
    const float* __restrict__ Wv,
    const float* __restrict__ W_ih, const float* __restrict__ W_hh,
    const float* __restrict__ b_ih, const float* __restrict__ b_hh,
    const float* __restrict__ W1,   const float* __restrict__ b1,
    const float* __restrict__ W2,   const float* __restrict__ b2,
    float* __restrict__ out, int last)
{
    __shared__ float U[8][64], slp[8][64], upds[8][64], updh[8][64];
    __shared__ float mln[8][64], snew[8][64];
    __shared__ float gi[8][192], gh[8][192];
    __shared__ float hh[8][128];
    __shared__ float Sg[8], Sb[8];
    __shared__ float lns[8][64], q[8][64], qt[8][64];

    int b = blockIdx.x, t = threadIdx.x;
    int w = t >> 5, l = t & 31;

    // reduce NBLKX per-block partials in fixed (deterministic) order
    const float* pb = g_part + (size_t)b * NBLKX * PREC;
    for (int i = t; i < PREC; i += 256) {
        float acc = 0.f;
#pragma unroll 8
        for (int blk = 0; blk < NBLKX; ++blk) acc += pb[(size_t)blk * PREC + i];
        if (i < 512)      U[i >> 6][i & 63] = acc;   // Pacc (temp)
        else if (i < 520) Sg[i - 512] = acc;
        else              Sb[i - 520] = acc;
    }
    for (int i = t; i < 512; i += 256) slp[i >> 6][i & 63] = g_slots[b * 512 + i];
    __syncthreads();

    // U[s,e] = (g_e*(Pacc - Sb[s]) + b_e*Sg[s]) / Sg[s]
    for (int i = t; i < 512; i += 256) {
        int s = i >> 6, e = i & 63;
        float P = fmaf(lng[e], U[s][e] - Sb[s], lnb[e] * Sg[s]);
        U[s][e] = P / Sg[s];
    }
    __syncthreads();

    // updates = U @ Wv^T
    for (int i = t; i < 512; i += 256) {
        int s = i >> 6, dd = i & 63;
        float acc = 0.f;
        const float* wr = Wv + dd * 64;
#pragma unroll 8
        for (int e = 0; e < 64; ++e) acc = fmaf(U[s][e], wr[e], acc);
        upds[s][dd] = acc;
    }
    __syncthreads();

    // GRU gate pre-activations
    for (int i = t; i < 1536; i += 256) {
        int s = i / 192, j = i % 192;
        float ai = b_ih[j], ah = b_hh[j];
        const float* wi = W_ih + j * 64;
        const float* whh = W_hh + j * 64;
#pragma unroll 8
        for (int dd = 0; dd < 64; ++dd) {
            ai = fmaf(upds[s][dd], wi[dd],  ai);
            ah = fmaf(slp[s][dd],  whh[dd], ah);
        }
        gi[s][j] = ai;
        gh[s][j] = ah;
    }
    __syncthreads();

    // gates + hidden update
    for (int i = t; i < 512; i += 256) {
        int s = i >> 6, dd = i & 63;
        float r = sigm(gi[s][dd]       + gh[s][dd]);
        float z = sigm(gi[s][64 + dd]  + gh[s][64 + dd]);
        float n = tanhf(fmaf(r, gh[s][128 + dd], gi[s][128 + dd]));
        updh[s][dd] = fmaf(z, slp[s][dd] - n, n);   // (1-z)*n + z*h
    }
    __syncthreads();

    // LN(updh) for the MLP: warp w handles slot w
    {
        float v0 = updh[w][l], v1 = updh[w][l + 32];
        float sum = v0 + v1;
        float sq  = fmaf(v0, v0, v1 * v1);
#pragma unroll
        for (int off = 16; off; off >>= 1) {
            sum += __shfl_xor_sync(0xffffffffu, sum, off);
            sq  += __shfl_xor_sync(0xffffffffu, sq,  off);
        }
        float m    = sum * (1.f / 64.f);
        float istd = rsqrtf(fmaf(sq, 1.f / 64.f, -m * m) + 1e-5f);
        mln[w][l]      = fmaf((v0 - m) * istd, lnmg[l],      lnmb[l]);
        mln[w][l + 32] = fmaf((v1 - m) * istd, lnmg[l + 32], lnmb[l + 32]);
    }
    __syncthreads();

    // hidden = relu(mln @ W1^T + b1)
    for (int i = t; i < 1024; i += 256) {
        int s = i >> 7, h = i & 127;
        float acc = b1[h];
        const float* wr = W1 + h * 64;
#pragma unroll 8
        for (int dd = 0; dd < 64; ++dd) acc = fmaf(mln[s][dd], wr[dd], acc);
        hh[s][h] = fmaxf(acc, 0.f);
    }
    __syncthreads();

    // slots_new = updh + hidden @ W2^T + b2
    for (int i = t; i < 512; i += 256) {
        int s = i >> 6, dd = i & 63;
        float acc = updh[s][dd] + b2[dd];
        const float* wr = W2 + dd * 128;
#pragma unroll 8
        for (int h = 0; h < 128; ++h) acc = fmaf(hh[s][h], wr[h], acc);
        snew[s][dd] = acc;
        g_slots[b * 512 + i] = acc;
        if (last) out[b * 512 + i] = acc;
    }
    __syncthreads();

    if (!last)
        prep_body(b, t, snew, lns, q, qt, lnsg, lnsb, Wq, Wk, lng, lnb);
}

// ---------------------------------------------------------------------------
extern "C" void kernel_launch(void* const* d_in, const int* in_sizes, int n_in,
                              void* d_out, int out_size)
{
    const float* x     = (const float*)d_in[0];
    const float* noise = (const float*)d_in[1];
    const float* mu    = (const float*)d_in[2];
    const float* lsig  = (const float*)d_in[3];
    const float* lng   = (const float*)d_in[4];
    const float* lnb   = (const float*)d_in[5];
    const float* lnsg  = (const float*)d_in[6];
    const float* lnsb  = (const float*)d_in[7];
    const float* lnmg  = (const float*)d_in[8];
    const float* lnmb  = (const float*)d_in[9];
    const float* Wq    = (const float*)d_in[10];
    const float* Wk    = (const float*)d_in[11];
    const float* Wv    = (const float*)d_in[12];
    const float* W_ih  = (const float*)d_in[13];
    const float* W_hh  = (const float*)d_in[14];
    const float* b_ih  = (const float*)d_in[15];
    const float* b_hh  = (const float*)d_in[16];
    const float* W1    = (const float*)d_in[17];
    const float* b1    = (const float*)d_in[18];
    const float* W2    = (const float*)d_in[19];
    const float* b2    = (const float*)d_in[20];
    float* out = (float*)d_out;

    k_init<<<BB, 256>>>(noise, mu, lsig, lnsg, lnsb, Wq, Wk, lng, lnb);

    for (int it = 0; it < 3; ++it) {
        k_pass<<<dim3(NBLKX, BB), PASS_THREADS>>>((const float4*)x);
        k_update<<<BB, 256>>>(lng, lnb, lnsg, lnsb, lnmg, lnmb,
                              Wq, Wk, Wv, W_ih, W_hh, b_ih, b_hh,
                              W1, b1, W2, b2, out, it == 2);
    }
}

// round 3
// speedup vs baseline: 2.3467x; 2.3467x over previous
#include <cuda_runtime.h>

// ---------------------------------------------------------------------------
// SlotAttention fused. B=32, N=16384, S=8, D=64, H=128, ITERS=3.
// Pass kernel: folded-LN logits + softmax + rank-1 accumulation in one sweep
// over raw x. f32x2 packed FMAs (exact fp32). Slot update kernels vectorized.
// ---------------------------------------------------------------------------

#define BB 32
#define NN 16384
#define SS 8
#define DD 64
#define HH 128
#define NBLKX 64
#define ROWS_PER_BLOCK 256
#define TILE_ROWS 128
#define NTILES 2
#define PREC 528                 // floats: 512 Pacc + 8 Sg + 8 Sb (= 132 float4)
#define PASS_THREADS 128

typedef unsigned long long ull;

__device__ float  g_slots[BB * SS * DD];
__device__ float4 g_wts4[BB * 128];          // [b][k=0..15][s=0..7]
__device__ float  g_c0[BB][SS];
__device__ float  g_c1[BB][SS];
__device__ float4 g_part4[(size_t)BB * NBLKX * 132];

#define F2FMA(d, a, b) asm("fma.rn.f32x2 %0, %1, %2, %0;" : "+l"(d) : "l"(a), "l"(b))
#define F2ADD(d, a, b) asm("add.rn.f32x2 %0, %1, %2;" : "=l"(d) : "l"(a), "l"(b))
#define F2PACK(v, lo, hi) asm("mov.b64 %0, {%1, %2};" : "=l"(v) : "f"(lo), "f"(hi))
#define F2UNPK(lo, hi, v) asm("mov.b64 {%0, %1}, %2;" : "=f"(lo), "=f"(hi) : "l"(v))

__device__ __forceinline__ float sigm(float x) { return 1.f / (1.f + __expf(-x)); }

__global__ void k_nop() {}   // shifts ncu -s 5 onto k_update#2 next profile

// ---------------------------------------------------------------------------
// prep: from slots (in shared) compute folded pass weights
// ---------------------------------------------------------------------------
__device__ __forceinline__ void prep_body(
    int b, int t,
    const float (*sl)[64], float (*lns)[64], float (*q)[64], float (*qt)[64],
    const float* __restrict__ lnsg, const float* __restrict__ lnsb,
    const float* __restrict__ Wq,   const float* __restrict__ Wk,
    const float* __restrict__ lng,  const float* __restrict__ lnb)
{
    int w = t >> 5, l = t & 31;
    {
        float v0 = sl[w][l], v1 = sl[w][l + 32];
        float sum = v0 + v1;
        float sq  = fmaf(v0, v0, v1 * v1);
#pragma unroll
        for (int off = 16; off; off >>= 1) {
            sum += __shfl_xor_sync(0xffffffffu, sum, off);
            sq  += __shfl_xor_sync(0xffffffffu, sq,  off);
        }
        float m    = sum * (1.f / 64.f);
        float istd = rsqrtf(fmaf(sq, 1.f / 64.f, -m * m) + 1e-5f);
        lns[w][l]      = fmaf((v0 - m) * istd, lnsg[l],      lnsb[l]);
        lns[w][l + 32] = fmaf((v1 - m) * istd, lnsg[l + 32], lnsb[l + 32]);
    }
    __syncthreads();
    // q = LN(slots) @ Wq^T * D^-0.5   (float4 dot)
    for (int i = t; i < 512; i += 256) {
        int s = i >> 6, dd = i & 63;
        const float4* wr = (const float4*)(Wq + dd * 64);
        const float4* lv = (const float4*)(lns[s]);
        float acc = 0.f;
#pragma unroll
        for (int e = 0; e < 16; ++e) {
            float4 a = lv[e], wv = wr[e];
            acc = fmaf(a.x, wv.x, fmaf(a.y, wv.y, fmaf(a.z, wv.z, fmaf(a.w, wv.w, acc))));
        }
        q[s][dd] = acc * 0.125f;
    }
    __syncthreads();
    // qtilde = q @ Wk  (coalesced over e)
    for (int i = t; i < 512; i += 256) {
        int s = i >> 6, e = i & 63;
        float acc = 0.f;
#pragma unroll 8
        for (int dd = 0; dd < 64; ++dd) acc = fmaf(q[s][dd], Wk[dd * 64 + e], acc);
        qt[s][e] = acc;
    }
    __syncthreads();
    float* wout = reinterpret_cast<float*>(g_wts4 + b * 128);
    for (int i = t; i < 512; i += 256) {
        int s = i >> 6, e = i & 63;
        int k = e >> 2, j = e & 3;
        wout[(k * 8 + s) * 4 + j] = lng[e] * qt[s][e];
    }
    if (t < 8) {
        float a0 = 0.f, a1 = 0.f;
#pragma unroll 8
        for (int e = 0; e < 64; ++e) {
            a1 = fmaf(lng[e], qt[t][e], a1);
            a0 = fmaf(lnb[e], qt[t][e], a0);
        }
        g_c1[b][t] = a1;
        g_c0[b][t] = a0;
    }
}

// ---------------------------------------------------------------------------
__global__ void __launch_bounds__(256) k_init(
    const float* __restrict__ noise, const float* __restrict__ mu,
    const float* __restrict__ lsig,
    const float* __restrict__ lnsg, const float* __restrict__ lnsb,
    const float* __restrict__ Wq,   const float* __restrict__ Wk,
    const float* __restrict__ lng,  const float* __restrict__ lnb)
{
    __shared__ __align__(16) float sl[8][64], lns[8][64], q[8][64], qt[8][64];
    int b = blockIdx.x, t = threadIdx.x;
    for (int i = t; i < 512; i += 256) {
        float v = fmaf(__expf(lsig[i]), noise[b * 512 + i], mu[i]);
        sl[i >> 6][i & 63] = v;
        g_slots[b * 512 + i] = v;
    }
    __syncthreads();
    prep_body(b, t, sl, lns, q, qt, lnsg, lnsb, Wq, Wk, lng, lnb);
}

// ---------------------------------------------------------------------------
// the big fused pass over x
// ---------------------------------------------------------------------------
__global__ void __launch_bounds__(PASS_THREADS, 5) k_pass(const float4* __restrict__ x4)
{
    __shared__ float4 xs[TILE_ROWS * 16];     // 32KB, swizzled rows
    __shared__ __align__(16) ull al_d[TILE_ROWS * 8]; // 8KB: dup'd alphas / pacc red
    __shared__ float4 wts[128];               // 2KB
    __shared__ float  c0s[8], c1s[8];
    __shared__ float  redSg[4][8], redSb[4][8];

    const int b = blockIdx.y;
    const int t = threadIdx.x;
    const int w = t >> 5, l = t & 31;

    wts[t] = g_wts4[b * 128 + t];
    if (t < 8) { c0s[t] = g_c0[b][t]; c1s[t] = g_c1[b][t]; }
    __syncthreads();

    float c0r[8], c1r[8], gacc[8], bacc[8];
    ull p2[8];
#pragma unroll
    for (int s = 0; s < 8; ++s) {
        c0r[s] = c0s[s]; c1r[s] = c1s[s];
        gacc[s] = 0.f; bacc[s] = 0.f; p2[s] = 0ULL;
    }

    const float4* xb = x4 + ((size_t)b * NN + (size_t)blockIdx.x * ROWS_PER_BLOCK) * 16;
    const ulonglong2* xs2 = reinterpret_cast<const ulonglong2*>(xs);
    const ulonglong2* wt2 = reinterpret_cast<const ulonglong2*>(wts);
    const ull*  xsu  = reinterpret_cast<const ull*>(xs);
    ulonglong2* ald2 = reinterpret_cast<ulonglong2*>(al_d);

#pragma unroll 1
    for (int tt = 0; tt < NTILES; ++tt) {
        // ---- stage 128 rows coalesced -> swizzled smem ----
        const float4* src = xb + (size_t)tt * TILE_ROWS * 16;
        const int kst = t & 15;
#pragma unroll
        for (int j = 0; j < 16; ++j) {
            int flat = j * 128 + t;
            int row  = flat >> 4;
            xs[row * 16 + (kst ^ (row & 15))] = src[flat];
        }
        __syncthreads();

        // ---- phase 1: lane t owns tile-row t ----
        {
            ull d2[8];
#pragma unroll
            for (int s = 0; s < 8; ++s) d2[s] = 0ULL;
            ull sum2 = 0ULL, sqa = 0ULL, sqb = 0ULL;
            const int xbase = t * 16, xo = t & 15;
#pragma unroll
            for (int k = 0; k < 16; ++k) {
                ulonglong2 v = xs2[xbase + (k ^ xo)];
                ull tv; F2ADD(tv, v.x, v.y); F2ADD(sum2, sum2, tv);
                F2FMA(sqa, v.x, v.x);
                F2FMA(sqb, v.y, v.y);
#pragma unroll
                for (int s = 0; s < 8; ++s) {
                    ulonglong2 wv = wt2[k * 8 + s];
                    F2FMA(d2[s], v.x, wv.x);
                    F2FMA(d2[s], v.y, wv.y);
                }
            }
            float slo, shi; F2UNPK(slo, shi, sum2);
            float sum = slo + shi;
            float qa0, qa1, qb0, qb1;
            F2UNPK(qa0, qa1, sqa); F2UNPK(qb0, qb1, sqb);
            float sq = (qa0 + qa1) + (qb0 + qb1);
            float m    = sum * (1.f / 64.f);
            float istd = rsqrtf(fmaf(sq, 1.f / 64.f, -m * m) + 1e-5f);
            float lo[8], mx = -3.4e38f;
#pragma unroll
            for (int s = 0; s < 8; ++s) {
                float dlo, dhi; F2UNPK(dlo, dhi, d2[s]);
                float d = dlo + dhi;
                lo[s] = fmaf(istd, fmaf(-m, c1r[s], d), c0r[s]);
                mx = fmaxf(mx, lo[s]);
            }
            float pr[8], ps = 0.f;
#pragma unroll
            for (int s = 0; s < 8; ++s) { pr[s] = __expf(lo[s] - mx); ps += pr[s]; }
            float rc  = 1.f / ps;
            float tmi = m * istd;
            ull aa[8];
#pragma unroll
            for (int s = 0; s < 8; ++s) {
                float a = fmaf(pr[s], rc, 1e-8f);    // softmax + EPS
                gacc[s] += a;
                bacc[s] = fmaf(a, tmi, bacc[s]);
                float al = a * istd;
                F2PACK(aa[s], al, al);               // duplicated pair
            }
#pragma unroll
            for (int i = 0; i < 4; ++i)
                ald2[t * 4 + i] = make_ulonglong2(aa[2 * i], aa[2 * i + 1]);
        }
        __syncwarp();

        // ---- phase 2: warp w covers rows w*32..w*32+31, all 8 slots ----
        {
            const int k4 = l >> 1, hf = l & 1;
#pragma unroll 4
            for (int j = 0; j < 32; ++j) {
                int r = w * 32 + j;
                ulonglong2 q0 = ald2[r * 4 + 0];
                ulonglong2 q1 = ald2[r * 4 + 1];
                ulonglong2 q2 = ald2[r * 4 + 2];
                ulonglong2 q3 = ald2[r * 4 + 3];
                ull xv = xsu[(r * 16 + (k4 ^ (r & 15))) * 2 + hf];
                F2FMA(p2[0], xv, q0.x); F2FMA(p2[1], xv, q0.y);
                F2FMA(p2[2], xv, q1.x); F2FMA(p2[3], xv, q1.y);
                F2FMA(p2[4], xv, q2.x); F2FMA(p2[5], xv, q2.y);
                F2FMA(p2[6], xv, q3.x); F2FMA(p2[7], xv, q3.y);
            }
        }
        __syncthreads();
    }

    // ---- deterministic cross-warp pacc reduce (reuse al_d) ----
#pragma unroll
    for (int s = 0; s < 8; ++s) al_d[w * 256 + s * 32 + l] = p2[s];

#pragma unroll
    for (int s = 0; s < 8; ++s) {
        float gv = gacc[s], bv = bacc[s];
#pragma unroll
        for (int off = 16; off; off >>= 1) {
            gv += __shfl_xor_sync(0xffffffffu, gv, off);
            bv += __shfl_xor_sync(0xffffffffu, bv, off);
        }
        if (l == 0) { redSg[w][s] = gv; redSb[w][s] = bv; }
    }
    __syncthreads();

    float* gp = reinterpret_cast<float*>(g_part4) +
                ((size_t)(b * NBLKX + blockIdx.x)) * PREC;
    const float2* rf = reinterpret_cast<const float2*>(al_d);
    float2* gp2 = reinterpret_cast<float2*>(gp);
#pragma unroll
    for (int ii = 0; ii < 2; ++ii) {
        int i = t + ii * 128;
        float2 a = rf[i], b2v = rf[256 + i], c = rf[512 + i], d = rf[768 + i];
        float2 o;
        o.x = ((a.x + b2v.x) + c.x) + d.x;
        o.y = ((a.y + b2v.y) + c.y) + d.y;
        gp2[i] = o;
    }
    if (t < 8) {
        gp[512 + t] = ((redSg[0][t] + redSg[1][t]) + redSg[2][t]) + redSg[3][t];
        gp[520 + t] = ((redSb[0][t] + redSb[1][t]) + redSb[2][t]) + redSb[3][t];
    }
}

// ---------------------------------------------------------------------------
// slot update (all weight dots float4-vectorized)
// ---------------------------------------------------------------------------
__global__ void __launch_bounds__(256) k_update(
    const float* __restrict__ lng,  const float* __restrict__ lnb,
    const float* __restrict__ lnsg, const float* __restrict__ lnsb,
    const float* __restrict__ lnmg, const float* __restrict__ lnmb,
    const float* __restrict__ Wq,   const float* __restrict__ Wk,
    const float* __restrict__ Wv,
    const float* __restrict__ W_ih, const float* __restrict__ W_hh,
    const float* __restrict__ b_ih, const float* __restrict__ b_hh,
    const float* __restrict__ W1,   const float* __restrict__ b1,
    const float* __restrict__ W2,   const float* __restrict__ b2,
    float* __restrict__ out, int last)
{
    __shared__ __align__(16) float U[8][64], slp[8][64], upds[8][64], updh[8][64];
    __shared__ __align__(16) float mln[8][64], snew[8][64];
    __shared__ __align__(16) float gi[8][192], gh[8][192];
    __shared__ __align__(16) float hh[8][128];
    __shared__ float Sg[8], Sb[8];
    __shared__ __align__(16) float lns[8][64], q[8][64], qt[8][64];

    int b = blockIdx.x, t = threadIdx.x;
    int w = t >> 5, l = t & 31;

    // fixed-order partial reduce, float4
    if (t < 132) {
        const float4* pb4 = g_part4 + (size_t)b * NBLKX * 132;
        float4 acc = make_float4(0.f, 0.f, 0.f, 0.f);
#pragma unroll 8
        for (int blk = 0; blk < NBLKX; ++blk) {
            float4 v = pb4[(size_t)blk * 132 + t];
            acc.x += v.x; acc.y += v.y; acc.z += v.z; acc.w += v.w;
        }
        int f = t * 4;
        if (f < 512) {
            int s = f >> 6, e = f & 63;
            U[s][e] = acc.x; U[s][e + 1] = acc.y; U[s][e + 2] = acc.z; U[s][e + 3] = acc.w;
        } else if (f == 512) { Sg[0]=acc.x; Sg[1]=acc.y; Sg[2]=acc.z; Sg[3]=acc.w; }
        else if (f == 516)   { Sg[4]=acc.x; Sg[5]=acc.y; Sg[6]=acc.z; Sg[7]=acc.w; }
        else if (f == 520)   { Sb[0]=acc.x; Sb[1]=acc.y; Sb[2]=acc.z; Sb[3]=acc.w; }
        else                 { Sb[4]=acc.x; Sb[5]=acc.y; Sb[6]=acc.z; Sb[7]=acc.w; }
    }
    for (int i = t; i < 512; i += 256) slp[i >> 6][i & 63] = g_slots[b * 512 + i];
    __syncthreads();

    // U[s,e] = (g_e*(Pacc - Sb[s]) + b_e*Sg[s]) / Sg[s]
    for (int i = t; i < 512; i += 256) {
        int s = i >> 6, e = i & 63;
        float P = fmaf(lng[e], U[s][e] - Sb[s], lnb[e] * Sg[s]);
        U[s][e] = P / Sg[s];
    }
    __syncthreads();

    // updates = U @ Wv^T
    for (int i = t; i < 512; i += 256) {
        int s = i >> 6, dd = i & 63;
        const float4* wr = (const float4*)(Wv + dd * 64);
        const float4* uv4 = (const float4*)(U[s]);
        float acc = 0.f;
#pragma unroll
        for (int e = 0; e < 16; ++e) {
            float4 a = uv4[e], wv = wr[e];
            acc = fmaf(a.x, wv.x, fmaf(a.y, wv.y, fmaf(a.z, wv.z, fmaf(a.w, wv.w, acc))));
        }
        upds[s][dd] = acc;
    }
    __syncthreads();

    // GRU pre-activations
    for (int i = t; i < 1536; i += 256) {
        int s = i / 192, j = i % 192;
        const float4* wi4 = (const float4*)(W_ih + j * 64);
        const float4* wh4 = (const float4*)(W_hh + j * 64);
        const float4* u4  = (const float4*)(upds[s]);
        const float4* h4  = (const float4*)(slp[s]);
        float ai = b_ih[j], ah = b_hh[j];
#pragma unroll
        for (int e = 0; e < 16; ++e) {
            float4 a = u4[e], wv = wi4[e];
            ai = fmaf(a.x, wv.x, fmaf(a.y, wv.y, fmaf(a.z, wv.z, fmaf(a.w, wv.w, ai))));
            float4 h = h4[e], wv2 = wh4[e];
            ah = fmaf(h.x, wv2.x, fmaf(h.y, wv2.y, fmaf(h.z, wv2.z, fmaf(h.w, wv2.w, ah))));
        }
        gi[s][j] = ai;
        gh[s][j] = ah;
    }
    __syncthreads();

    for (int i = t; i < 512; i += 256) {
        int s = i >> 6, dd = i & 63;
        float r = sigm(gi[s][dd]      + gh[s][dd]);
        float z = sigm(gi[s][64 + dd] + gh[s][64 + dd]);
        float n = tanhf(fmaf(r, gh[s][128 + dd], gi[s][128 + dd]));
        updh[s][dd] = fmaf(z, slp[s][dd] - n, n);
    }
    __syncthreads();

    // LN(updh)
    {
        float v0 = updh[w][l], v1 = updh[w][l + 32];
        float sum = v0 + v1;
        float sq  = fmaf(v0, v0, v1 * v1);
#pragma unroll
        for (int off = 16; off; off >>= 1) {
            sum += __shfl_xor_sync(0xffffffffu, sum, off);
            sq  += __shfl_xor_sync(0xffffffffu, sq,  off);
        }
        float m    = sum * (1.f / 64.f);
        float istd = rsqrtf(fmaf(sq, 1.f / 64.f, -m * m) + 1e-5f);
        mln[w][l]      = fmaf((v0 - m) * istd, lnmg[l],      lnmb[l]);
        mln[w][l + 32] = fmaf((v1 - m) * istd, lnmg[l + 32], lnmb[l + 32]);
    }
    __syncthreads();

    // hidden = relu(mln @ W1^T + b1)
    for (int i = t; i < 1024; i += 256) {
        int s = i >> 7, h = i & 127;
        const float4* wr = (const float4*)(W1 + h * 64);
        const float4* mv4 = (const float4*)(mln[s]);
        float acc = b1[h];
#pragma unroll
        for (int e = 0; e < 16; ++e) {
            float4 a = mv4[e], wv = wr[e];
            acc = fmaf(a.x, wv.x, fmaf(a.y, wv.y, fmaf(a.z, wv.z, fmaf(a.w, wv.w, acc))));
        }
        hh[s][h] = fmaxf(acc, 0.f);
    }
    __syncthreads();

    // slots_new = updh + hidden @ W2^T + b2
    for (int i = t; i < 512; i += 256) {
        int s = i >> 6, dd = i & 63;
        const float4* wr = (const float4*)(W2 + dd * 128);
        const float4* hv4 = (const float4*)(hh[s]);
        float acc = updh[s][dd] + b2[dd];
#pragma unroll
        for (int e = 0; e < 32; ++e) {
            float4 a = hv4[e], wv = wr[e];
            acc = fmaf(a.x, wv.x, fmaf(a.y, wv.y, fmaf(a.z, wv.z, fmaf(a.w, wv.w, acc))));
        }
        snew[s][dd] = acc;
        g_slots[b * 512 + i] = acc;
        if (last) out[b * 512 + i] = acc;
    }
    __syncthreads();

    if (!last)
        prep_body(b, t, snew, lns, q, qt, lnsg, lnsb, Wq, Wk, lng, lnb);
}

// ---------------------------------------------------------------------------
extern "C" void kernel_launch(void* const* d_in, const int* in_sizes, int n_in,
                              void* d_out, int out_size)
{
    const float* x     = (const float*)d_in[0];
    const float* noise = (const float*)d_in[1];
    const float* mu    = (const float*)d_in[2];
    const float* lsig  = (const float*)d_in[3];
    const float* lng   = (const float*)d_in[4];
    const float* lnb   = (const float*)d_in[5];
    const float* lnsg  = (const float*)d_in[6];
    const float* lnsb  = (const float*)d_in[7];
    const float* lnmg  = (const float*)d_in[8];
    const float* lnmb  = (const float*)d_in[9];
    const float* Wq    = (const float*)d_in[10];
    const float* Wk    = (const float*)d_in[11];
    const float* Wv    = (const float*)d_in[12];
    const float* W_ih  = (const float*)d_in[13];
    const float* W_hh  = (const float*)d_in[14];
    const float* b_ih  = (const float*)d_in[15];
    const float* b_hh  = (const float*)d_in[16];
    const float* W1    = (const float*)d_in[17];
    const float* b1    = (const float*)d_in[18];
    const float* W2    = (const float*)d_in[19];
    const float* b2    = (const float*)d_in[20];
    float* out = (float*)d_out;

    k_nop<<<1, 32>>>();   // aligns ncu -s 5 onto k_update#2
    k_init<<<BB, 256>>>(noise, mu, lsig, lnsg, lnsb, Wq, Wk, lng, lnb);

    for (int it = 0; it < 3; ++it) {
        k_pass<<<dim3(NBLKX, BB), PASS_THREADS>>>((const float4*)x);
        k_update<<<BB, 256>>>(lng, lnb, lnsg, lnsb, lnmg, lnmb,
                              Wq, Wk, Wv, W_ih, W_hh, b_ih, b_hh,
                              W1, b1, W2, b2, out, it == 2);
    }
}

// round 4
// speedup vs baseline: 3.2466x; 1.3835x over previous
#include <cuda_runtime.h>

// ---------------------------------------------------------------------------
// SlotAttention fused. B=32, N=16384, S=8, D=64, H=128, ITERS=3.
// k_pass: folded-LN logits + softmax + rank-1 accumulation (f32x2 FMAs).
// k_update/k_init: one block per (batch, slot) pair -> 256 blocks, latency
// hidden across SMs. All reductions fixed-order (deterministic).
// ---------------------------------------------------------------------------

#define BB 32
#define NN 16384
#define SS 8
#define DD 64
#define HH 128
#define NBLKX 64
#define ROWS_PER_BLOCK 256
#define TILE_ROWS 128
#define NTILES 2
#define PREC 528                 // floats per (b,blk): 512 Pacc + 8 Sg + 8 Sb
#define PASS_THREADS 128

typedef unsigned long long ull;

__device__ float  g_slots[BB * SS * DD];
__device__ float4 g_wts4[BB * 128];          // [b][k=0..15][s=0..7]
__device__ float  g_c0[BB][SS];
__device__ float  g_c1[BB][SS];
__device__ float4 g_part4[(size_t)BB * NBLKX * 132];

#define F2FMA(d, a, b) asm("fma.rn.f32x2 %0, %1, %2, %0;" : "+l"(d) : "l"(a), "l"(b))
#define F2ADD(d, a, b) asm("add.rn.f32x2 %0, %1, %2;" : "=l"(d) : "l"(a), "l"(b))
#define F2PACK(v, lo, hi) asm("mov.b64 %0, {%1, %2};" : "=l"(v) : "f"(lo), "f"(hi))
#define F2UNPK(lo, hi, v) asm("mov.b64 {%0, %1}, %2;" : "=f"(lo), "=f"(hi) : "l"(v))

__device__ __forceinline__ float sigm(float x) { return 1.f / (1.f + __expf(-x)); }

// dot of 16 float4 against 16 float4 (fixed order)
__device__ __forceinline__ float dot16x4(const float4* a, const float4* w, float acc) {
#pragma unroll
    for (int e = 0; e < 16; ++e) {
        float4 av = a[e], wv = w[e];
        acc = fmaf(av.x, wv.x, fmaf(av.y, wv.y, fmaf(av.z, wv.z, fmaf(av.w, wv.w, acc))));
    }
    return acc;
}
__device__ __forceinline__ float dot8x4(const float4* a, const float4* w) {
    float acc = 0.f;
#pragma unroll
    for (int e = 0; e < 8; ++e) {
        float4 av = a[e], wv = w[e];
        acc = fmaf(av.x, wv.x, fmaf(av.y, wv.y, fmaf(av.z, wv.z, fmaf(av.w, wv.w, acc))));
    }
    return acc;
}

// warp0 LayerNorm of 64 values in smem -> out (g,b applied)
__device__ __forceinline__ void ln64_warp(const float* in, float* out,
                                          const float* __restrict__ g,
                                          const float* __restrict__ bt, int t) {
    if (t < 32) {
        float v0 = in[t], v1 = in[t + 32];
        float sum = v0 + v1;
        float sq  = fmaf(v0, v0, v1 * v1);
#pragma unroll
        for (int off = 16; off; off >>= 1) {
            sum += __shfl_xor_sync(0xffffffffu, sum, off);
            sq  += __shfl_xor_sync(0xffffffffu, sq,  off);
        }
        float m    = sum * (1.f / 64.f);
        float istd = rsqrtf(fmaf(sq, 1.f / 64.f, -m * m) + 1e-5f);
        out[t]      = fmaf((v0 - m) * istd, g[t],      bt[t]);
        out[t + 32] = fmaf((v1 - m) * istd, g[t + 32], bt[t + 32]);
    }
}

// ---------------------------------------------------------------------------
// per-(b,s) prep: folded pass weights for next iteration
// needs smem scratch: lns[64], qv[64], qtv[64], hpart[128]
// ---------------------------------------------------------------------------
__device__ __forceinline__ void prep_slot(
    int b, int s, int t,
    const float* snew, float* lns, float* qv, float* qtv, float* hpart,
    const float* __restrict__ lnsg, const float* __restrict__ lnsb,
    const float* __restrict__ Wq,   const float* __restrict__ Wk,
    const float* __restrict__ lng,  const float* __restrict__ lnb)
{
    ln64_warp(snew, lns, lnsg, lnsb, t);
    __syncthreads();
    // q[dd] = lns . Wq[dd,:] * 0.125, split into two halves
    {
        int dd = t & 63, h = t >> 6;
        const float4* wr = (const float4*)(Wq + dd * 64) + h * 8;
        const float4* lv = (const float4*)lns + h * 8;
        hpart[t] = dot8x4(lv, wr);
    }
    __syncthreads();
    if (t < 64) qv[t] = (hpart[t] + hpart[t + 64]) * 0.125f;
    __syncthreads();
    // qt[e] = sum_dd q[dd] * Wk[dd,e]  (coalesced over e), half-split over dd
    {
        int e = t & 63, h = t >> 6;
        float acc = 0.f;
        const float* wk = Wk + (h * 32) * 64 + e;
#pragma unroll 8
        for (int dd = 0; dd < 32; ++dd) acc = fmaf(qv[h * 32 + dd], wk[dd * 64], acc);
        hpart[t] = acc;
    }
    __syncthreads();
    if (t < 64) qtv[t] = hpart[t] + hpart[t + 64];
    __syncthreads();
    if (t < 64) {
        int k = t >> 2, j = t & 3;
        reinterpret_cast<float*>(g_wts4 + b * 128)[(k * 8 + s) * 4 + j] = lng[t] * qtv[t];
    }
    if (t < 32) {
        float p1 = fmaf(lng[t + 32], qtv[t + 32], lng[t] * qtv[t]);
        float p0 = fmaf(lnb[t + 32], qtv[t + 32], lnb[t] * qtv[t]);
#pragma unroll
        for (int off = 16; off; off >>= 1) {
            p1 += __shfl_xor_sync(0xffffffffu, p1, off);
            p0 += __shfl_xor_sync(0xffffffffu, p0, off);
        }
        if (t == 0) { g_c1[b][s] = p1; g_c0[b][s] = p0; }
    }
}

// ---------------------------------------------------------------------------
__global__ void __launch_bounds__(128) k_init(
    const float* __restrict__ noise, const float* __restrict__ mu,
    const float* __restrict__ lsig,
    const float* __restrict__ lnsg, const float* __restrict__ lnsb,
    const float* __restrict__ Wq,   const float* __restrict__ Wk,
    const float* __restrict__ lng,  const float* __restrict__ lnb)
{
    __shared__ __align__(16) float snew[64], lns[64], qv[64], qtv[64], hpart[128];
    int bs = blockIdx.x, b = bs >> 3, s = bs & 7, t = threadIdx.x;
    if (t < 64) {
        int idx = s * 64 + t;
        float v = fmaf(__expf(lsig[idx]), noise[b * 512 + idx], mu[idx]);
        snew[t] = v;
        g_slots[b * 512 + idx] = v;
    }
    __syncthreads();
    prep_slot(b, s, t, snew, lns, qv, qtv, hpart, lnsg, lnsb, Wq, Wk, lng, lnb);
}

// ---------------------------------------------------------------------------
// the big fused pass over x (unchanged from round 2)
// ---------------------------------------------------------------------------
__global__ void __launch_bounds__(PASS_THREADS, 5) k_pass(const float4* __restrict__ x4)
{
    __shared__ float4 xs[TILE_ROWS * 16];
    __shared__ __align__(16) ull al_d[TILE_ROWS * 8];
    __shared__ float4 wts[128];
    __shared__ float  c0s[8], c1s[8];
    __shared__ float  redSg[4][8], redSb[4][8];

    const int b = blockIdx.y;
    const int t = threadIdx.x;
    const int w = t >> 5, l = t & 31;

    wts[t] = g_wts4[b * 128 + t];
    if (t < 8) { c0s[t] = g_c0[b][t]; c1s[t] = g_c1[b][t]; }
    __syncthreads();

    float c0r[8], c1r[8], gacc[8], bacc[8];
    ull p2[8];
#pragma unroll
    for (int s = 0; s < 8; ++s) {
        c0r[s] = c0s[s]; c1r[s] = c1s[s];
        gacc[s] = 0.f; bacc[s] = 0.f; p2[s] = 0ULL;
    }

    const float4* xb = x4 + ((size_t)b * NN + (size_t)blockIdx.x * ROWS_PER_BLOCK) * 16;
    const ulonglong2* xs2 = reinterpret_cast<const ulonglong2*>(xs);
    const ulonglong2* wt2 = reinterpret_cast<const ulonglong2*>(wts);
    const ull*  xsu  = reinterpret_cast<const ull*>(xs);
    ulonglong2* ald2 = reinterpret_cast<ulonglong2*>(al_d);

#pragma unroll 1
    for (int tt = 0; tt < NTILES; ++tt) {
        const float4* src = xb + (size_t)tt * TILE_ROWS * 16;
        const int kst = t & 15;
#pragma unroll
        for (int j = 0; j < 16; ++j) {
            int flat = j * 128 + t;
            int row  = flat >> 4;
            xs[row * 16 + (kst ^ (row & 15))] = src[flat];
        }
        __syncthreads();

        {
            ull d2[8];
#pragma unroll
            for (int s = 0; s < 8; ++s) d2[s] = 0ULL;
            ull sum2 = 0ULL, sqa = 0ULL, sqb = 0ULL;
            const int xbase = t * 16, xo = t & 15;
#pragma unroll
            for (int k = 0; k < 16; ++k) {
                ulonglong2 v = xs2[xbase + (k ^ xo)];
                ull tv; F2ADD(tv, v.x, v.y); F2ADD(sum2, sum2, tv);
                F2FMA(sqa, v.x, v.x);
                F2FMA(sqb, v.y, v.y);
#pragma unroll
                for (int s = 0; s < 8; ++s) {
                    ulonglong2 wv = wt2[k * 8 + s];
                    F2FMA(d2[s], v.x, wv.x);
                    F2FMA(d2[s], v.y, wv.y);
                }
            }
            float slo, shi; F2UNPK(slo, shi, sum2);
            float sum = slo + shi;
            float qa0, qa1, qb0, qb1;
            F2UNPK(qa0, qa1, sqa); F2UNPK(qb0, qb1, sqb);
            float sq = (qa0 + qa1) + (qb0 + qb1);
            float m    = sum * (1.f / 64.f);
            float istd = rsqrtf(fmaf(sq, 1.f / 64.f, -m * m) + 1e-5f);
            float lo[8], mx = -3.4e38f;
#pragma unroll
            for (int s = 0; s < 8; ++s) {
                float dlo, dhi; F2UNPK(dlo, dhi, d2[s]);
                float d = dlo + dhi;
                lo[s] = fmaf(istd, fmaf(-m, c1r[s], d), c0r[s]);
                mx = fmaxf(mx, lo[s]);
            }
            float pr[8], ps = 0.f;
#pragma unroll
            for (int s = 0; s < 8; ++s) { pr[s] = __expf(lo[s] - mx); ps += pr[s]; }
            float rc  = 1.f / ps;
            float tmi = m * istd;
            ull aa[8];
#pragma unroll
            for (int s = 0; s < 8; ++s) {
                float a = fmaf(pr[s], rc, 1e-8f);
                gacc[s] += a;
                bacc[s] = fmaf(a, tmi, bacc[s]);
                float al = a * istd;
                F2PACK(aa[s], al, al);
            }
#pragma unroll
            for (int i = 0; i < 4; ++i)
                ald2[t * 4 + i] = make_ulonglong2(aa[2 * i], aa[2 * i + 1]);
        }
        __syncwarp();

        {
            const int k4 = l >> 1, hf = l & 1;
#pragma unroll 4
            for (int j = 0; j < 32; ++j) {
                int r = w * 32 + j;
                ulonglong2 q0 = ald2[r * 4 + 0];
                ulonglong2 q1 = ald2[r * 4 + 1];
                ulonglong2 q2 = ald2[r * 4 + 2];
                ulonglong2 q3 = ald2[r * 4 + 3];
                ull xv = xsu[(r * 16 + (k4 ^ (r & 15))) * 2 + hf];
                F2FMA(p2[0], xv, q0.x); F2FMA(p2[1], xv, q0.y);
                F2FMA(p2[2], xv, q1.x); F2FMA(p2[3], xv, q1.y);
                F2FMA(p2[4], xv, q2.x); F2FMA(p2[5], xv, q2.y);
                F2FMA(p2[6], xv, q3.x); F2FMA(p2[7], xv, q3.y);
            }
        }
        __syncthreads();
    }

#pragma unroll
    for (int s = 0; s < 8; ++s) al_d[w * 256 + s * 32 + l] = p2[s];

#pragma unroll
    for (int s = 0; s < 8; ++s) {
        float gv = gacc[s], bv = bacc[s];
#pragma unroll
        for (int off = 16; off; off >>= 1) {
            gv += __shfl_xor_sync(0xffffffffu, gv, off);
            bv += __shfl_xor_sync(0xffffffffu, bv, off);
        }
        if (l == 0) { redSg[w][s] = gv; redSb[w][s] = bv; }
    }
    __syncthreads();

    float* gp = reinterpret_cast<float*>(g_part4) +
                ((size_t)(b * NBLKX + blockIdx.x)) * PREC;
    const float2* rf = reinterpret_cast<const float2*>(al_d);
    float2* gp2 = reinterpret_cast<float2*>(gp);
#pragma unroll
    for (int ii = 0; ii < 2; ++ii) {
        int i = t + ii * 128;
        float2 a = rf[i], b2v = rf[256 + i], c = rf[512 + i], d = rf[768 + i];
        float2 o;
        o.x = ((a.x + b2v.x) + c.x) + d.x;
        o.y = ((a.y + b2v.y) + c.y) + d.y;
        gp2[i] = o;
    }
    if (t < 8) {
        gp[512 + t] = ((redSg[0][t] + redSg[1][t]) + redSg[2][t]) + redSg[3][t];
        gp[520 + t] = ((redSb[0][t] + redSb[1][t]) + redSb[2][t]) + redSb[3][t];
    }
}

// ---------------------------------------------------------------------------
// slot update: one block per (b,s). 128 threads, half-split dots.
// ---------------------------------------------------------------------------
__global__ void __launch_bounds__(128) k_update(
    const float* __restrict__ lng,  const float* __restrict__ lnb,
    const float* __restrict__ lnsg, const float* __restrict__ lnsb,
    const float* __restrict__ lnmg, const float* __restrict__ lnmb,
    const float* __restrict__ Wq,   const float* __restrict__ Wk,
    const float* __restrict__ Wv,
    const float* __restrict__ W_ih, const float* __restrict__ W_hh,
    const float* __restrict__ b_ih, const float* __restrict__ b_hh,
    const float* __restrict__ W1,   const float* __restrict__ b1,
    const float* __restrict__ W2,   const float* __restrict__ b2,
    float* __restrict__ out, int last)
{
    __shared__ __align__(16) float P[64], Uv[64], upds[64], slp[64];
    __shared__ __align__(16) float gi[192], gh[192], updh[64], mln[64];
    __shared__ __align__(16) float hhs[128], snew[64];
    __shared__ __align__(16) float lns[64], qv[64], qtv[64], hpart[128];
    __shared__ float sred[4];
    __shared__ float sSg, sSb;

    int bs = blockIdx.x, b = bs >> 3, s = bs & 7, t = threadIdx.x;

    // ---- A: reduce 64 per-block partials for this slot (fixed order) ----
    const float* pb = reinterpret_cast<const float*>(g_part4) + (size_t)b * NBLKX * PREC;
    {
        int e = t & 63, h = t >> 6;
        const float* src = pb + (size_t)h * 32 * PREC + s * 64 + e;
        float acc = 0.f;
#pragma unroll 8
        for (int blk = 0; blk < 32; ++blk) acc += src[(size_t)blk * PREC];
        hpart[t] = acc;
    }
    if (t < 4) {
        int which = t & 1, h = t >> 1;          // 0=Sg, 1=Sb
        const float* src = pb + (size_t)h * 32 * PREC + 512 + which * 8 + s;
        float acc = 0.f;
#pragma unroll 8
        for (int blk = 0; blk < 32; ++blk) acc += src[(size_t)blk * PREC];
        sred[t] = acc;
    }
    if (t < 64) slp[t] = g_slots[b * 512 + s * 64 + t];
    __syncthreads();
    if (t < 64) P[t] = hpart[t] + hpart[t + 64];
    if (t == 0) { sSg = sred[0] + sred[2]; sSb = sred[1] + sred[3]; }
    __syncthreads();

    // ---- B: U[e] = (g*(P - Sb) + b*Sg)/Sg ----
    if (t < 64) Uv[t] = fmaf(lng[t], P[t] - sSb, lnb[t] * sSg) / sSg;
    __syncthreads();

    // ---- C: upds = U @ Wv^T (half-split) ----
    {
        int dd = t & 63, h = t >> 6;
        const float4* wr = (const float4*)(Wv + dd * 64) + h * 8;
        const float4* uv = (const float4*)Uv + h * 8;
        float r = dot8x4(uv, wr);
        __syncthreads();               // hpart WAR
        hpart[t] = r;
    }
    __syncthreads();
    if (t < 64) upds[t] = hpart[t] + hpart[t + 64];
    __syncthreads();

    // ---- D: GRU pre-activations (384 full dots / 128 threads = 3 each) ----
#pragma unroll
    for (int k = 0; k < 3; ++k) {
        int id = t + 128 * k;
        if (id < 192) {
            int j = id;
            gi[j] = dot16x4((const float4*)upds, (const float4*)(W_ih + j * 64), b_ih[j]);
        } else {
            int j = id - 192;
            gh[j] = dot16x4((const float4*)slp, (const float4*)(W_hh + j * 64), b_hh[j]);
        }
    }
    __syncthreads();

    // ---- E: gates ----
    if (t < 64) {
        float r = sigm(gi[t]      + gh[t]);
        float z = sigm(gi[64 + t] + gh[64 + t]);
        float n = tanhf(fmaf(r, gh[128 + t], gi[128 + t]));
        updh[t] = fmaf(z, slp[t] - n, n);
    }
    __syncthreads();

    // ---- F: LN(updh) ----
    ln64_warp(updh, mln, lnmg, lnmb, t);
    __syncthreads();

    // ---- G: hidden = relu(mln @ W1^T + b1), 128 outputs ----
    hhs[t] = fmaxf(dot16x4((const float4*)mln, (const float4*)(W1 + t * 64), b1[t]), 0.f);
    __syncthreads();

    // ---- H: snew = updh + hh @ W2^T + b2 (half-split over 128) ----
    {
        int dd = t & 63, h = t >> 6;
        const float4* wr = (const float4*)(W2 + dd * 128) + h * 16;
        const float4* hv = (const float4*)hhs + h * 16;
        hpart[t] = dot16x4(hv, wr, 0.f);
    }
    __syncthreads();
    if (t < 64) {
        float v = updh[t] + b2[t] + (hpart[t] + hpart[t + 64]);
        snew[t] = v;
        g_slots[b * 512 + s * 64 + t] = v;
        if (last) out[b * 512 + s * 64 + t] = v;
    }
    __syncthreads();

    if (!last)
        prep_slot(b, s, t, snew, lns, qv, qtv, hpart, lnsg, lnsb, Wq, Wk, lng, lnb);
}

// ---------------------------------------------------------------------------
extern "C" void kernel_launch(void* const* d_in, const int* in_sizes, int n_in,
                              void* d_out, int out_size)
{
    const float* x     = (const float*)d_in[0];
    const float* noise = (const float*)d_in[1];
    const float* mu    = (const float*)d_in[2];
    const float* lsig  = (const float*)d_in[3];
    const float* lng   = (const float*)d_in[4];
    const float* lnb   = (const float*)d_in[5];
    const float* lnsg  = (const float*)d_in[6];
    const float* lnsb  = (const float*)d_in[7];
    const float* lnmg  = (const float*)d_in[8];
    const float* lnmb  = (const float*)d_in[9];
    const float* Wq    = (const float*)d_in[10];
    const float* Wk    = (const float*)d_in[11];
    const float* Wv    = (const float*)d_in[12];
    const float* W_ih  = (const float*)d_in[13];
    const float* W_hh  = (const float*)d_in[14];
    const float* b_ih  = (const float*)d_in[15];
    const float* b_hh  = (const float*)d_in[16];
    const float* W1    = (const float*)d_in[17];
    const float* b1    = (const float*)d_in[18];
    const float* W2    = (const float*)d_in[19];
    const float* b2    = (const float*)d_in[20];
    float* out = (float*)d_out;

    k_init<<<BB * SS, 128>>>(noise, mu, lsig, lnsg, lnsb, Wq, Wk, lng, lnb);

    for (int it = 0; it < 3; ++it) {
        k_pass<<<dim3(NBLKX, BB), PASS_THREADS>>>((const float4*)x);
        k_update<<<BB * SS, 128>>>(lng, lnb, lnsg, lnsb, lnmg, lnmb,
                                   Wq, Wk, Wv, W_ih, W_hh, b_ih, b_hh,
                                   W1, b1, W2, b2, out, it == 2);
    }
}

// round 6
// speedup vs baseline: 4.4934x; 1.3840x over previous
#include <cuda_runtime.h>

// ---------------------------------------------------------------------------
// SlotAttention fused. B=32, N=16384, S=8, D=64, H=128, ITERS=3.
// k_pass: per-warp cp.async pipelined tiles (32 rows/warp-tile, ring depth 2),
//         folded-LN logits + softmax + rank-1 accumulation, f32x2 FMAs,
//         no block-level syncs in the mainloop.
// k_update/k_init: one block per (batch, slot). Fixed-order reductions.
// ---------------------------------------------------------------------------

#define BB 32
#define NN 16384
#define SS 8
#define DD 64
#define HH 128
#define NBLKX 32                 // pass blocks per batch (512 rows each)
#define WTILES 4                 // warp-tiles per warp (32 rows each)
#define PREC 528                 // floats per record: 512 Pacc + 8 Sg + 8 Sb
#define PASS_THREADS 128
// smem: xs 4096*16 + as4 256*16 + wts 128*16 + tail 80*4 = 72000 -> pad 72064
#define SMEM_BYTES 72064

typedef unsigned long long ull;

__device__ float  g_slots[BB * SS * DD];
__device__ float4 g_wts4[BB * 128];          // [b][k=0..15][s=0..7]
__device__ float  g_c0[BB][SS];
__device__ float  g_c1[BB][SS];
__device__ float4 g_part4[(size_t)BB * NBLKX * 132];

#define F2FMA(d, a, b) asm("fma.rn.f32x2 %0, %1, %2, %0;" : "+l"(d) : "l"(a), "l"(b))
#define F2ADD(d, a, b) asm("add.rn.f32x2 %0, %1, %2;" : "=l"(d) : "l"(a), "l"(b))
#define F2PACK(v, lo, hi) asm("mov.b64 %0, {%1, %2};" : "=l"(v) : "f"(lo), "f"(hi))
#define F2UNPK(lo, hi, v) asm("mov.b64 {%0, %1}, %2;" : "=f"(lo), "=f"(hi) : "l"(v))

__device__ __forceinline__ float sigm(float x) { return 1.f / (1.f + __expf(-x)); }

__device__ __forceinline__ float dot16x4(const float4* a, const float4* w, float acc) {
#pragma unroll
    for (int e = 0; e < 16; ++e) {
        float4 av = a[e], wv = w[e];
        acc = fmaf(av.x, wv.x, fmaf(av.y, wv.y, fmaf(av.z, wv.z, fmaf(av.w, wv.w, acc))));
    }
    return acc;
}
__device__ __forceinline__ float dot8x4(const float4* a, const float4* w) {
    float acc = 0.f;
#pragma unroll
    for (int e = 0; e < 8; ++e) {
        float4 av = a[e], wv = w[e];
        acc = fmaf(av.x, wv.x, fmaf(av.y, wv.y, fmaf(av.z, wv.z, fmaf(av.w, wv.w, acc))));
    }
    return acc;
}

__device__ __forceinline__ void ln64_warp(const float* in, float* out,
                                          const float* __restrict__ g,
                                          const float* __restrict__ bt, int t) {
    if (t < 32) {
        float v0 = in[t], v1 = in[t + 32];
        float sum = v0 + v1;
        float sq  = fmaf(v0, v0, v1 * v1);
#pragma unroll
        for (int off = 16; off; off >>= 1) {
            sum += __shfl_xor_sync(0xffffffffu, sum, off);
            sq  += __shfl_xor_sync(0xffffffffu, sq,  off);
        }
        float m    = sum * (1.f / 64.f);
        float istd = rsqrtf(fmaf(sq, 1.f / 64.f, -m * m) + 1e-5f);
        out[t]      = fmaf((v0 - m) * istd, g[t],      bt[t]);
        out[t + 32] = fmaf((v1 - m) * istd, g[t + 32], bt[t + 32]);
    }
}

// ---------------------------------------------------------------------------
__device__ __forceinline__ void prep_slot(
    int b, int s, int t,
    const float* snew, float* lns, float* qv, float* qtv, float* hpart,
    const float* __restrict__ lnsg, const float* __restrict__ lnsb,
    const float* __restrict__ Wq,   const float* __restrict__ Wk,
    const float* __restrict__ lng,  const float* __restrict__ lnb)
{
    ln64_warp(snew, lns, lnsg, lnsb, t);
    __syncthreads();
    {
        int dd = t & 63, h = t >> 6;
        const float4* wr = (const float4*)(Wq + dd * 64) + h * 8;
        const float4* lv = (const float4*)lns + h * 8;
        hpart[t] = dot8x4(lv, wr);
    }
    __syncthreads();
    if (t < 64) qv[t] = (hpart[t] + hpart[t + 64]) * 0.125f;
    __syncthreads();
    {
        int e = t & 63, h = t >> 6;
        float acc = 0.f;
        const float* wk = Wk + (h * 32) * 64 + e;
#pragma unroll 8
        for (int dd = 0; dd < 32; ++dd) acc = fmaf(qv[h * 32 + dd], wk[dd * 64], acc);
        hpart[t] = acc;
    }
    __syncthreads();
    if (t < 64) qtv[t] = hpart[t] + hpart[t + 64];
    __syncthreads();
    if (t < 64) {
        int k = t >> 2, j = t & 3;
        reinterpret_cast<float*>(g_wts4 + b * 128)[(k * 8 + s) * 4 + j] = lng[t] * qtv[t];
    }
    if (t < 32) {
        float p1 = fmaf(lng[t + 32], qtv[t + 32], lng[t] * qtv[t]);
        float p0 = fmaf(lnb[t + 32], qtv[t + 32], lnb[t] * qtv[t]);
#pragma unroll
        for (int off = 16; off; off >>= 1) {
            p1 += __shfl_xor_sync(0xffffffffu, p1, off);
            p0 += __shfl_xor_sync(0xffffffffu, p0, off);
        }
        if (t == 0) { g_c1[b][s] = p1; g_c0[b][s] = p0; }
    }
}

// ---------------------------------------------------------------------------
__global__ void __launch_bounds__(128) k_init(
    const float* __restrict__ noise, const float* __restrict__ mu,
    const float* __restrict__ lsig,
    const float* __restrict__ lnsg, const float* __restrict__ lnsb,
    const float* __restrict__ Wq,   const float* __restrict__ Wk,
    const float* __restrict__ lng,  const float* __restrict__ lnb)
{
    __shared__ __align__(16) float snew[64], lns[64], qv[64], qtv[64], hpart[128];
    int bs = blockIdx.x, b = bs >> 3, s = bs & 7, t = threadIdx.x;
    if (t < 64) {
        int idx = s * 64 + t;
        float v = fmaf(__expf(lsig[idx]), noise[b * 512 + idx], mu[idx]);
        snew[t] = v;
        g_slots[b * 512 + idx] = v;
    }
    __syncthreads();
    prep_slot(b, s, t, snew, lns, qv, qtv, hpart, lnsg, lnsb, Wq, Wk, lng, lnb);
}

// ---------------------------------------------------------------------------
// stage one 32-row warp-tile (8KB) via cp.async (lane l issues 16 x 16B)
// ---------------------------------------------------------------------------
__device__ __forceinline__ void stage_tile(const float4* __restrict__ gsrc,
                                           unsigned sdst, int l)
{
#pragma unroll
    for (int j = 0; j < 16; ++j) {
        int flat = j * 32 + l;
        int row = flat >> 4, k = flat & 15;
        unsigned dst = sdst + (unsigned)((row * 16 + (k ^ (row & 15))) * 16);
        asm volatile("cp.async.cg.shared.global [%0], [%1], 16;"
                     :: "r"(dst), "l"(gsrc + flat));
    }
    asm volatile("cp.async.commit_group;");
}

// ---------------------------------------------------------------------------
// the big fused pass. dynamic smem layout (float4 units):
//   [0,4096)    xs   : 4 warps x 2 ring x 512 (64KB)
//   [4096,4352) as4  : 4 warps x 64 (4KB)
//   [4352,4480) wts  : 128 (2KB)
//   tail floats: c0s[8], c1s[8], redSg[4][8], redSb[4][8]
// ---------------------------------------------------------------------------
__global__ void __launch_bounds__(PASS_THREADS) k_pass(const float4* __restrict__ x4)
{
    extern __shared__ __align__(16) float4 smem[];
    float4* xs   = smem;
    float4* as4  = smem + 4096;
    float4* wts  = smem + 4352;
    float*  tail = (float*)(smem + 4480);   // 80 floats

    const int b = blockIdx.y;
    const int t = threadIdx.x;
    const int w = t >> 5, l = t & 31;

    unsigned smem_u32;
    { size_t a = __cvta_generic_to_shared(xs); smem_u32 = (unsigned)a; }
    const unsigned xs_base = smem_u32 + (unsigned)(w * 1024 * 16);

    // prologue: prefetch warp-tiles 0 and 1
    const float4* gwarp = x4 + ((size_t)b * NN + (size_t)blockIdx.x * 512 + w * 128) * 16;
    stage_tile(gwarp,       xs_base,        l);
    stage_tile(gwarp + 512, xs_base + 8192, l);

    wts[t] = g_wts4[b * 128 + t];
    if (t < 8)  tail[t]     = g_c0[b][t];
    if (t >= 8 && t < 16) tail[t] = g_c1[b][t - 8];
    __syncthreads();

    float c0r[8], c1r[8], gacc[8], bacc[8];
    ull p2[8];
#pragma unroll
    for (int s = 0; s < 8; ++s) {
        c0r[s] = tail[s]; c1r[s] = tail[8 + s];
        gacc[s] = 0.f; bacc[s] = 0.f; p2[s] = 0ULL;
    }

    const ulonglong2* wt2 = reinterpret_cast<const ulonglong2*>(wts);
    float4* as4w = as4 + w * 64;
    const int g2 = l >> 4, e4 = l & 15;

#pragma unroll
    for (int tl = 0; tl < WTILES; ++tl) {
        if (tl == WTILES - 1) asm volatile("cp.async.wait_group 0;" ::: "memory");
        else                  asm volatile("cp.async.wait_group 1;" ::: "memory");
        __syncwarp();

        const ulonglong2* xs2w = reinterpret_cast<const ulonglong2*>(
            xs + w * 1024 + (tl & 1) * 512);

        // ---- phase 1: lane l owns row l of this 32-row tile ----
        {
            ull d2[8];
#pragma unroll
            for (int s = 0; s < 8; ++s) d2[s] = 0ULL;
            ull sum2 = 0ULL, sqa = 0ULL, sqb = 0ULL;
            const int rb = l * 16, ro = l & 15;
#pragma unroll
            for (int k = 0; k < 16; ++k) {
                ulonglong2 v = xs2w[rb + (k ^ ro)];
                ull tv; F2ADD(tv, v.x, v.y); F2ADD(sum2, sum2, tv);
                F2FMA(sqa, v.x, v.x);
                F2FMA(sqb, v.y, v.y);
#pragma unroll
                for (int s = 0; s < 8; ++s) {
                    ulonglong2 wv = wt2[k * 8 + s];
                    F2FMA(d2[s], v.x, wv.x);
                    F2FMA(d2[s], v.y, wv.y);
                }
            }
            float slo, shi; F2UNPK(slo, shi, sum2);
            float sum = slo + shi;
            float qa0, qa1, qb0, qb1;
            F2UNPK(qa0, qa1, sqa); F2UNPK(qb0, qb1, sqb);
            float sq = (qa0 + qa1) + (qb0 + qb1);
            float m    = sum * (1.f / 64.f);
            float istd = rsqrtf(fmaf(sq, 1.f / 64.f, -m * m) + 1e-5f);
            float lo[8], mx = -3.4e38f;
#pragma unroll
            for (int s = 0; s < 8; ++s) {
                float dlo, dhi; F2UNPK(dlo, dhi, d2[s]);
                float d = dlo + dhi;
                lo[s] = fmaf(istd, fmaf(-m, c1r[s], d), c0r[s]);
                mx = fmaxf(mx, lo[s]);
            }
            float pr[8], ps = 0.f;
#pragma unroll
            for (int s = 0; s < 8; ++s) { pr[s] = __expf(lo[s] - mx); ps += pr[s]; }
            float rc  = 1.f / ps;
            float tmi = m * istd;
            float al[8];
#pragma unroll
            for (int s = 0; s < 8; ++s) {
                float a = fmaf(pr[s], rc, 1e-8f);   // softmax + EPS
                gacc[s] += a;
                bacc[s] = fmaf(a, tmi, bacc[s]);
                al[s]   = a * istd;
            }
            as4w[l * 2 + 0] = make_float4(al[0], al[1], al[2], al[3]);
            as4w[l * 2 + 1] = make_float4(al[4], al[5], al[6], al[7]);
        }
        __syncwarp();

        // ---- phase 2: lane (g2, e4) owns slots 4g2..4g2+3 x elems 4e4..4e4+3 ----
#pragma unroll 4
        for (int r = 0; r < 32; ++r) {
            float4 av = as4w[r * 2 + g2];
            ulonglong2 xq = xs2w[r * 16 + (e4 ^ (r & 15))];
            ull a0, a1, a2, a3;
            F2PACK(a0, av.x, av.x); F2PACK(a1, av.y, av.y);
            F2PACK(a2, av.z, av.z); F2PACK(a3, av.w, av.w);
            F2FMA(p2[0], xq.x, a0); F2FMA(p2[1], xq.y, a0);
            F2FMA(p2[2], xq.x, a1); F2FMA(p2[3], xq.y, a1);
            F2FMA(p2[4], xq.x, a2); F2FMA(p2[5], xq.y, a2);
            F2FMA(p2[6], xq.x, a3); F2FMA(p2[7], xq.y, a3);
        }
        __syncwarp();

        if (tl < WTILES - 2)
            stage_tile(gwarp + (tl + 2) * 512, xs_base + (tl & 1) * 8192, l);
    }

    // ---- Sg/Sb warp reduce ----
#pragma unroll
    for (int s = 0; s < 8; ++s) {
        float gv = gacc[s], bv = bacc[s];
#pragma unroll
        for (int off = 16; off; off >>= 1) {
            gv += __shfl_xor_sync(0xffffffffu, gv, off);
            bv += __shfl_xor_sync(0xffffffffu, bv, off);
        }
        if (l == 0) { tail[16 + w * 8 + s] = gv; tail[48 + w * 8 + s] = bv; }
    }
    __syncthreads();   // all warps done; xs reusable as reduction scratch

    // ---- cross-warp Pacc reduce (fixed order) ----
    float4* red4 = xs;   // [w][128] float4 = [w][s*16+e4]
#pragma unroll
    for (int ss = 0; ss < 4; ++ss) {
        float x0, x1, x2, x3;
        F2UNPK(x0, x1, p2[2 * ss]);
        F2UNPK(x2, x3, p2[2 * ss + 1]);
        red4[w * 128 + (4 * g2 + ss) * 16 + e4] = make_float4(x0, x1, x2, x3);
    }
    __syncthreads();

    float4* gp4 = g_part4 + ((size_t)(b * NBLKX + blockIdx.x)) * 132;
    {
        float4 a = red4[t], bb2 = red4[128 + t], c = red4[256 + t], d = red4[384 + t];
        float4 o;
        o.x = ((a.x + bb2.x) + c.x) + d.x;
        o.y = ((a.y + bb2.y) + c.y) + d.y;
        o.z = ((a.z + bb2.z) + c.z) + d.z;
        o.w = ((a.w + bb2.w) + c.w) + d.w;
        gp4[t] = o;
    }
    if (t < 16) {
        const float* src = tail + 16 + (t >= 8 ? 32 : 0) + (t & 7);
        float v = ((src[0] + src[8]) + src[16]) + src[24];
        reinterpret_cast<float*>(gp4)[512 + (t >= 8 ? 8 : 0) + (t & 7)] = v;
    }
}

// ---------------------------------------------------------------------------
// slot update: one block per (b,s)
// ---------------------------------------------------------------------------
__global__ void __launch_bounds__(128) k_update(
    const float* __restrict__ lng,  const float* __restrict__ lnb,
    const float* __restrict__ lnsg, const float* __restrict__ lnsb,
    const float* __restrict__ lnmg, const float* __restrict__ lnmb,
    const float* __restrict__ Wq,   const float* __restrict__ Wk,
    const float* __restrict__ Wv,
    const float* __restrict__ W_ih, const float* __restrict__ W_hh,
    const float* __restrict__ b_ih, const float* __restrict__ b_hh,
    const float* __restrict__ W1,   const float* __restrict__ b1,
    const float* __restrict__ W2,   const float* __restrict__ b2,
    float* __restrict__ out, int last)
{
    __shared__ __align__(16) float P[64], Uv[64], upds[64], slp[64];
    __shared__ __align__(16) float gi[192], gh[192], updh[64], mln[64];
    __shared__ __align__(16) float hhs[128], snew[64];
    __shared__ __align__(16) float lns[64], qv[64], qtv[64], hpart[128];
    __shared__ float sred[4];
    __shared__ float sSg, sSb;

    int bs = blockIdx.x, b = bs >> 3, s = bs & 7, t = threadIdx.x;

    const float* pb = reinterpret_cast<const float*>(g_part4) + (size_t)b * NBLKX * PREC;
    {
        int e = t & 63, h = t >> 6;
        const float* src = pb + (size_t)h * 16 * PREC + s * 64 + e;
        float acc = 0.f;
#pragma unroll 8
        for (int blk = 0; blk < 16; ++blk) acc += src[(size_t)blk * PREC];
        hpart[t] = acc;
    }
    if (t < 4) {
        int which = t & 1, h = t >> 1;
        const float* src = pb + (size_t)h * 16 * PREC + 512 + which * 8 + s;
        float acc = 0.f;
#pragma unroll 8
        for (int blk = 0; blk < 16; ++blk) acc += src[(size_t)blk * PREC];
        sred[t] = acc;
    }
    if (t < 64) slp[t] = g_slots[b * 512 + s * 64 + t];
    __syncthreads();
    if (t < 64) P[t] = hpart[t] + hpart[t + 64];
    if (t == 0) { sSg = sred[0] + sred[2]; sSb = sred[1] + sred[3]; }
    __syncthreads();

    if (t < 64) Uv[t] = fmaf(lng[t], P[t] - sSb, lnb[t] * sSg) / sSg;
    __syncthreads();

    {
        int dd = t & 63, h = t >> 6;
        const float4* wr = (const float4*)(Wv + dd * 64) + h * 8;
        const float4* uv = (const float4*)Uv + h * 8;
        float r = dot8x4(uv, wr);
        __syncthreads();
        hpart[t] = r;
    }
    __syncthreads();
    if (t < 64) upds[t] = hpart[t] + hpart[t + 64];
    __syncthreads();

#pragma unroll
    for (int k = 0; k < 3; ++k) {
        int id = t + 128 * k;
        if (id < 192) {
            int j = id;
            gi[j] = dot16x4((const float4*)upds, (const float4*)(W_ih + j * 64), b_ih[j]);
        } else {
            int j = id - 192;
            gh[j] = dot16x4((const float4*)slp, (const float4*)(W_hh + j * 64), b_hh[j]);
        }
    }
    __syncthreads();

    if (t < 64) {
        float r = sigm(gi[t]      + gh[t]);
        float z = sigm(gi[64 + t] + gh[64 + t]);
        float n = tanhf(fmaf(r, gh[128 + t], gi[128 + t]));
        updh[t] = fmaf(z, slp[t] - n, n);
    }
    __syncthreads();

    ln64_warp(updh, mln, lnmg, lnmb, t);
    __syncthreads();

    hhs[t] = fmaxf(dot16x4((const float4*)mln, (const float4*)(W1 + t * 64), b1[t]), 0.f);
    __syncthreads();

    {
        int dd = t & 63, h = t >> 6;
        const float4* wr = (const float4*)(W2 + dd * 128) + h * 16;
        const float4* hv = (const float4*)hhs + h * 16;
        hpart[t] = dot16x4(hv, wr, 0.f);
    }
    __syncthreads();
    if (t < 64) {
        float v = updh[t] + b2[t] + (hpart[t] + hpart[t + 64]);
        snew[t] = v;
        g_slots[b * 512 + s * 64 + t] = v;
        if (last) out[b * 512 + s * 64 + t] = v;
    }
    __syncthreads();

    if (!last)
        prep_slot(b, s, t, snew, lns, qv, qtv, hpart, lnsg, lnsb, Wq, Wk, lng, lnb);
}

// ---------------------------------------------------------------------------
extern "C" void kernel_launch(void* const* d_in, const int* in_sizes, int n_in,
                              void* d_out, int out_size)
{
    const float* x     = (const float*)d_in[0];
    const float* noise = (const float*)d_in[1];
    const float* mu    = (const float*)d_in[2];
    const float* lsig  = (const float*)d_in[3];
    const float* lng   = (const float*)d_in[4];
    const float* lnb   = (const float*)d_in[5];
    const float* lnsg  = (const float*)d_in[6];
    const float* lnsb  = (const float*)d_in[7];
    const float* lnmg  = (const float*)d_in[8];
    const float* lnmb  = (const float*)d_in[9];
    const float* Wq    = (const float*)d_in[10];
    const float* Wk    = (const float*)d_in[11];
    const float* Wv    = (const float*)d_in[12];
    const float* W_ih  = (const float*)d_in[13];
    const float* W_hh  = (const float*)d_in[14];
    const float* b_ih  = (const float*)d_in[15];
    const float* b_hh  = (const float*)d_in[16];
    const float* W1    = (const float*)d_in[17];
    const float* b1    = (const float*)d_in[18];
    const float* W2    = (const float*)d_in[19];
    const float* b2    = (const float*)d_in[20];
    float* out = (float*)d_out;

    cudaFuncSetAttribute(k_pass, cudaFuncAttributeMaxDynamicSharedMemorySize, SMEM_BYTES);

    k_init<<<BB * SS, 128>>>(noise, mu, lsig, lnsg, lnsb, Wq, Wk, lng, lnb);

    for (int it = 0; it < 3; ++it) {
        k_pass<<<dim3(NBLKX, BB), PASS_THREADS, SMEM_BYTES>>>((const float4*)x);
        k_update<<<BB * SS, 128>>>(lng, lnb, lnsg, lnsb, lnmg, lnmb,
                                   Wq, Wk, Wv, W_ih, W_hh, b_ih, b_hh,
                                   W1, b1, W2, b2, out, it == 2);
    }
}